// round 5
// baseline (speedup 1.0000x reference)
#include <cuda_runtime.h>
#include <cstdint>

// Problem constants (fixed by the dataset)
#define NN 500000
#define GG 1000
#define TB 256

// ---------------------------------------------------------------------------
// Scratch (device globals).
// g_deg[n]: lo16 = deg_in, hi16 = deg_out (max degree ~50 << 65535).
// ---------------------------------------------------------------------------
__device__ unsigned g_deg [NN];
__device__ float    g_agg1[NN];   // layer-1 scalar aggregation
__device__ float    g_t   [NN];   // s * isi * iso (layer-2 propagand)
__device__ float    g_A   [NN];   // layer-2 scalar aggregation
__device__ float    g_S   [GG];   // pooled scalar sum per graph
__device__ float    g_cnt [GG];   // nodes per graph
__device__ unsigned g_count;      // grid-barrier arrivals (self-cleaning)
__device__ unsigned g_done;       // end-of-kernel handshake (self-cleaning)

#define ONE_IN  1u
#define ONE_OUT (1u << 16)

__device__ __forceinline__ void red_f32(float* p, float v) {
    asm volatile("red.global.add.f32 [%0], %1;" :: "l"(p), "f"(v) : "memory");
}
__device__ __forceinline__ void red_u32(unsigned* p, unsigned v) {
    asm volatile("red.global.add.u32 [%0], %1;" :: "l"(p), "r"(v) : "memory");
}

// Grid-wide barrier: all nb blocks arrive, spin until barrier #phase complete.
// Monotonic counter (no mid-kernel reset -> no reset race). Requires all nb
// blocks co-resident (guaranteed by occupancy-sized launch).
__device__ __forceinline__ void gsync(unsigned nb, unsigned phase) {
    __threadfence();          // make this block's REDs/stores visible
    __syncthreads();
    if (threadIdx.x == 0) {
        unsigned target = nb * phase;
        atomicAdd(&g_count, 1u);
        while (*(volatile unsigned*)&g_count < target)
            __nanosleep(64);
    }
    __syncthreads();
    __threadfence();          // acquire: order subsequent loads after spin
}

__device__ __forceinline__ float x0_of(unsigned p) {
    float di = (float)(p & 0xffffu);
    float dq = (float)(p >> 16);
    return di * rsqrtf(fmaxf(dq, 1.0f));
}

// ---------------------------------------------------------------------------
// The whole pipeline in one persistent kernel.
// ---------------------------------------------------------------------------
__global__ void __launch_bounds__(TB)
k_fused(const float* __restrict__ W1, const float* __restrict__ W2,
        const float* __restrict__ Wlast,
        const int* __restrict__ src, const int* __restrict__ dst,
        const int* __restrict__ gid,
        float* __restrict__ out, int E, int N, int G, unsigned nb)
{
    const unsigned tid = blockIdx.x * TB + threadIdx.x;
    const unsigned nt  = nb * TB;
    const unsigned nE8 = ((unsigned)E + 7u) >> 3;

    // ---- P0: zero accumulators -------------------------------------------
    for (unsigned i = tid; i < (unsigned)N; i += nt) {
        g_deg[i] = 0u; g_agg1[i] = 0.0f; g_A[i] = 0.0f;
    }
    for (unsigned i = tid; i < GG; i += nt) { g_S[i] = 0.0f; g_cnt[i] = 0.0f; }
    gsync(nb, 1);

    // ---- P1: degree histogram (packed u16|u16, red.u32) -------------------
    for (unsigned c = tid; c < nE8; c += nt) {
        int base = (int)(c << 3);
        if (base + 7 < E) {
            int4 s0 = *reinterpret_cast<const int4*>(src + base);
            int4 s1 = *reinterpret_cast<const int4*>(src + base + 4);
            int4 d0 = *reinterpret_cast<const int4*>(dst + base);
            int4 d1 = *reinterpret_cast<const int4*>(dst + base + 4);
            red_u32(&g_deg[s0.x], ONE_OUT); red_u32(&g_deg[s0.y], ONE_OUT);
            red_u32(&g_deg[s0.z], ONE_OUT); red_u32(&g_deg[s0.w], ONE_OUT);
            red_u32(&g_deg[s1.x], ONE_OUT); red_u32(&g_deg[s1.y], ONE_OUT);
            red_u32(&g_deg[s1.z], ONE_OUT); red_u32(&g_deg[s1.w], ONE_OUT);
            red_u32(&g_deg[d0.x], ONE_IN);  red_u32(&g_deg[d0.y], ONE_IN);
            red_u32(&g_deg[d0.z], ONE_IN);  red_u32(&g_deg[d0.w], ONE_IN);
            red_u32(&g_deg[d1.x], ONE_IN);  red_u32(&g_deg[d1.y], ONE_IN);
            red_u32(&g_deg[d1.z], ONE_IN);  red_u32(&g_deg[d1.w], ONE_IN);
        } else {
            for (int e = base; e < E; ++e) {
                red_u32(&g_deg[src[e]], ONE_OUT);
                red_u32(&g_deg[dst[e]], ONE_IN);
            }
        }
    }
    gsync(nb, 2);

    // ---- P2: layer-1 scatter, x0 inline ------------------------------------
    for (unsigned c = tid; c < nE8; c += nt) {
        int base = (int)(c << 3);
        if (base + 7 < E) {
            int4 s0 = *reinterpret_cast<const int4*>(src + base);
            int4 s1 = *reinterpret_cast<const int4*>(src + base + 4);
            int4 d0 = *reinterpret_cast<const int4*>(dst + base);
            int4 d1 = *reinterpret_cast<const int4*>(dst + base + 4);
            float v0 = x0_of(__ldg(&g_deg[s0.x]));
            float v1 = x0_of(__ldg(&g_deg[s0.y]));
            float v2 = x0_of(__ldg(&g_deg[s0.z]));
            float v3 = x0_of(__ldg(&g_deg[s0.w]));
            float v4 = x0_of(__ldg(&g_deg[s1.x]));
            float v5 = x0_of(__ldg(&g_deg[s1.y]));
            float v6 = x0_of(__ldg(&g_deg[s1.z]));
            float v7 = x0_of(__ldg(&g_deg[s1.w]));
            red_f32(&g_agg1[d0.x], v0); red_f32(&g_agg1[d0.y], v1);
            red_f32(&g_agg1[d0.z], v2); red_f32(&g_agg1[d0.w], v3);
            red_f32(&g_agg1[d1.x], v4); red_f32(&g_agg1[d1.y], v5);
            red_f32(&g_agg1[d1.z], v6); red_f32(&g_agg1[d1.w], v7);
        } else {
            for (int e = base; e < E; ++e)
                red_f32(&g_agg1[dst[e]], x0_of(__ldg(&g_deg[src[e]])));
        }
    }
    gsync(nb, 3);

    // ---- P3: t = agg1 * isi * iso ------------------------------------------
    for (unsigned i = tid; i < (unsigned)N; i += nt) {
        unsigned p = g_deg[i];
        float isi = rsqrtf(fmaxf((float)(p & 0xffffu), 1.0f));
        float iso = rsqrtf(fmaxf((float)(p >> 16), 1.0f));
        g_t[i] = g_agg1[i] * isi * iso;
    }
    gsync(nb, 4);

    // ---- P4: layer-2 scatter ------------------------------------------------
    for (unsigned c = tid; c < nE8; c += nt) {
        int base = (int)(c << 3);
        if (base + 7 < E) {
            int4 s0 = *reinterpret_cast<const int4*>(src + base);
            int4 s1 = *reinterpret_cast<const int4*>(src + base + 4);
            int4 d0 = *reinterpret_cast<const int4*>(dst + base);
            int4 d1 = *reinterpret_cast<const int4*>(dst + base + 4);
            float v0 = __ldg(&g_t[s0.x]);
            float v1 = __ldg(&g_t[s0.y]);
            float v2 = __ldg(&g_t[s0.z]);
            float v3 = __ldg(&g_t[s0.w]);
            float v4 = __ldg(&g_t[s1.x]);
            float v5 = __ldg(&g_t[s1.y]);
            float v6 = __ldg(&g_t[s1.z]);
            float v7 = __ldg(&g_t[s1.w]);
            red_f32(&g_A[d0.x], v0); red_f32(&g_A[d0.y], v1);
            red_f32(&g_A[d0.z], v2); red_f32(&g_A[d0.w], v3);
            red_f32(&g_A[d1.x], v4); red_f32(&g_A[d1.y], v5);
            red_f32(&g_A[d1.z], v6); red_f32(&g_A[d1.w], v7);
        } else {
            for (int e = base; e < E; ++e)
                red_f32(&g_A[dst[e]], __ldg(&g_t[src[e]]));
        }
    }
    gsync(nb, 5);

    // ---- P5: pooling (sorted gid -> warp-uniform fast path) -----------------
    {
        unsigned lane = threadIdx.x & 31u;
        unsigned wbase = blockIdx.x * TB + (threadIdx.x & ~31u);
        for (unsigned b = wbase; b < (unsigned)N; b += nt) {   // b warp-uniform
            unsigned i = b + lane;
            bool valid = (i < (unsigned)N);
            float u = 0.0f;
            int g = -1;
            if (valid) {
                unsigned p = g_deg[i];
                u = g_A[i] * rsqrtf(fmaxf((float)(p & 0xffffu), 1.0f));
                g = gid[i];
            }
            int  g0  = __shfl_sync(0xffffffffu, g, 0);
            bool uni = __all_sync(0xffffffffu, valid && (g == g0));
            if (uni) {
#pragma unroll
                for (int o = 16; o > 0; o >>= 1)
                    u += __shfl_xor_sync(0xffffffffu, u, o);
                if (lane == 0) {
                    red_f32(&g_S[g0], u);
                    red_f32(&g_cnt[g0], 32.0f);
                }
            } else if (valid) {
                red_f32(&g_S[g], u);
                red_f32(&g_cnt[g], 1.0f);
            }
        }
    }
    gsync(nb, 6);

    // ---- P6: out[g][c] = (S_g/max(cnt_g,1)) * rW_c --------------------------
    for (unsigned t = tid; t < (unsigned)(G * 8); t += nt) {
        unsigned g = t >> 3;
        unsigned c = t & 7u;
        float rw = 0.0f;
#pragma unroll
        for (int k = 0; k < 8; ++k) {
            float q = 0.0f;
#pragma unroll
            for (int j = 0; j < 8; ++j)
                q += fmaxf(__ldg(&W1[j]), 0.0f) * __ldg(&W2[j * 8 + k]);
            rw += fmaxf(q, 0.0f) * __ldg(&Wlast[k * 8 + c]);
        }
        out[t] = (g_S[g] / fmaxf(g_cnt[g], 1.0f)) * rw;
    }

    // ---- self-cleaning reset of barrier state (race-free handshake) --------
    __threadfence();
    __syncthreads();
    if (threadIdx.x == 0) {
        unsigned v = atomicAdd(&g_done, 1u) + 1u;
        if (v == nb) {               // all blocks are past the final barrier
            g_done  = 0u;
            g_count = 0u;
            __threadfence();
        }
    }
}

// ---------------------------------------------------------------------------
// kernel_launch — single cooperative-style persistent kernel, one graph node.
// Inputs (metadata order): W1[8], W2[64], Wlast[64], src[E], dst[E], graph_ids[N]
// Output: G*C float32
// ---------------------------------------------------------------------------
extern "C" void kernel_launch(void* const* d_in, const int* in_sizes, int n_in,
                              void* d_out, int out_size) {
    const float* W1    = (const float*)d_in[0];
    const float* W2    = (const float*)d_in[1];
    const float* Wlast = (const float*)d_in[2];
    const int*   src   = (const int*)d_in[3];
    const int*   dst   = (const int*)d_in[4];
    const int*   gid   = (const int*)d_in[5];

    int E = in_sizes[3];
    int N = in_sizes[5];
    int G = out_size / 8;
    float* out = (float*)d_out;

    // Co-residency-safe grid size (host-side queries; capture-legal).
    int dev = 0;
    cudaGetDevice(&dev);
    int nsm = 0;
    cudaDeviceGetAttribute(&nsm, cudaDevAttrMultiProcessorCount, dev);
    int bpm = 0;
    cudaOccupancyMaxActiveBlocksPerMultiprocessor(&bpm, k_fused, TB, 0);
    if (bpm < 1) bpm = 1;
    unsigned nb = (unsigned)(nsm * bpm);
    // Don't launch more blocks than the largest phase can use.
    unsigned nE8 = ((unsigned)E + 7u) >> 3;
    unsigned need = (nE8 + TB - 1) / TB;
    if (nb > need) nb = need;
    if (nb < 1u) nb = 1u;

    k_fused<<<nb, TB>>>(W1, W2, Wlast, src, dst, gid, out, E, N, G, nb);
}

// round 6
// speedup vs baseline: 1.1153x; 1.1153x over previous
#include <cuda_runtime.h>
#include <cstdint>

// Problem constants (fixed by the dataset)
#define NN 500000
#define GG 1000

// ---------------------------------------------------------------------------
// Scratch: ONE contiguous zeroed region (single memset node) + t (not zeroed).
//   [0,        2e6)  deg  : u32 per node, lo16 = deg_in, hi16 = deg_out
//   [2e6,      4e6)  agg1 : f32 per node
//   [4e6,      6e6)  A    : f32 per node
//   [6e6,      6e6+4k)   S   : f32 per graph
//   [6e6+4k,   6e6+8k)   cnt : f32 per graph
// ---------------------------------------------------------------------------
#define OFF_AGG1 (NN * 4)
#define OFF_A    (NN * 8)
#define OFF_S    (NN * 12)
#define OFF_CNT  (NN * 12 + GG * 4)
#define BUF_BYTES (NN * 12 + GG * 8)

__device__ __align__(128) unsigned char g_buf[BUF_BYTES];
__device__ float    g_t[NN];
__device__ unsigned g_ticket;   // last-block-done counter (self-resetting)

#define G_DEG  ((unsigned*)g_buf)
#define G_AGG1 ((float*)(g_buf + OFF_AGG1))
#define G_A    ((float*)(g_buf + OFF_A))
#define G_S    ((float*)(g_buf + OFF_S))
#define G_CNT  ((float*)(g_buf + OFF_CNT))

#define ONE_IN  1u
#define ONE_OUT (1u << 16)

__device__ __forceinline__ void red_f32(float* p, float v) {
    asm volatile("red.global.add.f32 [%0], %1;" :: "l"(p), "f"(v) : "memory");
}
__device__ __forceinline__ void red_u32(unsigned* p, unsigned v) {
    asm volatile("red.global.add.u32 [%0], %1;" :: "l"(p), "r"(v) : "memory");
}

// ---------------------------------------------------------------------------
// K1: degree counting, packed u32 (u16 in | u16 out). 8 edges / thread.
// ---------------------------------------------------------------------------
__global__ void k_deg(const int* __restrict__ src, const int* __restrict__ dst, int E) {
    int i = blockIdx.x * blockDim.x + threadIdx.x;
    int base = i << 3;
    unsigned* deg = G_DEG;
    if (base + 7 < E) {
        int4 s0 = *reinterpret_cast<const int4*>(src + base);
        int4 s1 = *reinterpret_cast<const int4*>(src + base + 4);
        int4 d0 = *reinterpret_cast<const int4*>(dst + base);
        int4 d1 = *reinterpret_cast<const int4*>(dst + base + 4);
        red_u32(&deg[s0.x], ONE_OUT); red_u32(&deg[s0.y], ONE_OUT);
        red_u32(&deg[s0.z], ONE_OUT); red_u32(&deg[s0.w], ONE_OUT);
        red_u32(&deg[s1.x], ONE_OUT); red_u32(&deg[s1.y], ONE_OUT);
        red_u32(&deg[s1.z], ONE_OUT); red_u32(&deg[s1.w], ONE_OUT);
        red_u32(&deg[d0.x], ONE_IN);  red_u32(&deg[d0.y], ONE_IN);
        red_u32(&deg[d0.z], ONE_IN);  red_u32(&deg[d0.w], ONE_IN);
        red_u32(&deg[d1.x], ONE_IN);  red_u32(&deg[d1.y], ONE_IN);
        red_u32(&deg[d1.z], ONE_IN);  red_u32(&deg[d1.w], ONE_IN);
    } else {
        for (int e = base; e < E; ++e) {
            red_u32(&deg[src[e]], ONE_OUT);
            red_u32(&deg[dst[e]], ONE_IN);
        }
    }
}

// ---------------------------------------------------------------------------
// K2: layer-1 scatter with inline x0. 8 edges / thread.
// ---------------------------------------------------------------------------
__device__ __forceinline__ float x0_of(unsigned p) {
    float di = (float)(p & 0xffffu);
    float dq = (float)(p >> 16);
    return di * rsqrtf(fmaxf(dq, 1.0f));
}

__global__ void k_scatter1(const int* __restrict__ src, const int* __restrict__ dst, int E) {
    int i = blockIdx.x * blockDim.x + threadIdx.x;
    int base = i << 3;
    const unsigned* deg = G_DEG;
    float* agg1 = G_AGG1;
    if (base + 7 < E) {
        int4 s0 = *reinterpret_cast<const int4*>(src + base);
        int4 s1 = *reinterpret_cast<const int4*>(src + base + 4);
        int4 d0 = *reinterpret_cast<const int4*>(dst + base);
        int4 d1 = *reinterpret_cast<const int4*>(dst + base + 4);
        float v0 = x0_of(__ldg(&deg[s0.x]));
        float v1 = x0_of(__ldg(&deg[s0.y]));
        float v2 = x0_of(__ldg(&deg[s0.z]));
        float v3 = x0_of(__ldg(&deg[s0.w]));
        float v4 = x0_of(__ldg(&deg[s1.x]));
        float v5 = x0_of(__ldg(&deg[s1.y]));
        float v6 = x0_of(__ldg(&deg[s1.z]));
        float v7 = x0_of(__ldg(&deg[s1.w]));
        red_f32(&agg1[d0.x], v0); red_f32(&agg1[d0.y], v1);
        red_f32(&agg1[d0.z], v2); red_f32(&agg1[d0.w], v3);
        red_f32(&agg1[d1.x], v4); red_f32(&agg1[d1.y], v5);
        red_f32(&agg1[d1.z], v6); red_f32(&agg1[d1.w], v7);
    } else {
        for (int e = base; e < E; ++e)
            red_f32(&agg1[dst[e]], x0_of(__ldg(&deg[src[e]])));
    }
}

// ---------------------------------------------------------------------------
// K3: t = agg1 * isi * iso — vectorized, 4 nodes / thread.
// ---------------------------------------------------------------------------
__global__ void k_t(int N) {
    int i = blockIdx.x * blockDim.x + threadIdx.x;
    int base = i << 2;
    if (base + 3 < N) {
        uint4  p = *reinterpret_cast<const uint4*>(G_DEG + base);
        float4 a = *reinterpret_cast<const float4*>(G_AGG1 + base);
        float4 r;
        r.x = a.x * rsqrtf(fmaxf((float)(p.x & 0xffffu), 1.0f)) * rsqrtf(fmaxf((float)(p.x >> 16), 1.0f));
        r.y = a.y * rsqrtf(fmaxf((float)(p.y & 0xffffu), 1.0f)) * rsqrtf(fmaxf((float)(p.y >> 16), 1.0f));
        r.z = a.z * rsqrtf(fmaxf((float)(p.z & 0xffffu), 1.0f)) * rsqrtf(fmaxf((float)(p.z >> 16), 1.0f));
        r.w = a.w * rsqrtf(fmaxf((float)(p.w & 0xffffu), 1.0f)) * rsqrtf(fmaxf((float)(p.w >> 16), 1.0f));
        *reinterpret_cast<float4*>(g_t + base) = r;
    } else {
        for (int n = base; n < N; ++n) {
            unsigned p = G_DEG[n];
            g_t[n] = G_AGG1[n]
                   * rsqrtf(fmaxf((float)(p & 0xffffu), 1.0f))
                   * rsqrtf(fmaxf((float)(p >> 16), 1.0f));
        }
    }
}

// ---------------------------------------------------------------------------
// K4: layer-2 scalar scatter  A[dst] += t[src].  8 edges / thread.
// ---------------------------------------------------------------------------
__global__ void k_scatter2(const int* __restrict__ src, const int* __restrict__ dst, int E) {
    int i = blockIdx.x * blockDim.x + threadIdx.x;
    int base = i << 3;
    float* A = G_A;
    if (base + 7 < E) {
        int4 s0 = *reinterpret_cast<const int4*>(src + base);
        int4 s1 = *reinterpret_cast<const int4*>(src + base + 4);
        int4 d0 = *reinterpret_cast<const int4*>(dst + base);
        int4 d1 = *reinterpret_cast<const int4*>(dst + base + 4);
        float v0 = __ldg(&g_t[s0.x]);
        float v1 = __ldg(&g_t[s0.y]);
        float v2 = __ldg(&g_t[s0.z]);
        float v3 = __ldg(&g_t[s0.w]);
        float v4 = __ldg(&g_t[s1.x]);
        float v5 = __ldg(&g_t[s1.y]);
        float v6 = __ldg(&g_t[s1.z]);
        float v7 = __ldg(&g_t[s1.w]);
        red_f32(&A[d0.x], v0); red_f32(&A[d0.y], v1);
        red_f32(&A[d0.z], v2); red_f32(&A[d0.w], v3);
        red_f32(&A[d1.x], v4); red_f32(&A[d1.y], v5);
        red_f32(&A[d1.z], v6); red_f32(&A[d1.w], v7);
    } else {
        for (int e = base; e < E; ++e)
            red_f32(&A[dst[e]], __ldg(&g_t[src[e]]));
    }
}

// ---------------------------------------------------------------------------
// K5: pooling + fused final output (last-block-done pattern).
//     u = A * isi;  S[g] += u; cnt[g] += 1  (sorted gid -> warp fast path).
//     The last block to finish computes out[g][c] = (S/max(cnt,1)) * rW_c.
// ---------------------------------------------------------------------------
__global__ void k_pool_final(const int* __restrict__ gid,
                             const float* __restrict__ W1, const float* __restrict__ W2,
                             const float* __restrict__ Wlast,
                             float* __restrict__ out, int N, int G, unsigned nb) {
    int i = blockIdx.x * blockDim.x + threadIdx.x;
    bool valid = (i < N);
    float u = 0.0f;
    int g = -1;
    if (valid) {
        unsigned p = G_DEG[i];
        u = G_A[i] * rsqrtf(fmaxf((float)(p & 0xffffu), 1.0f));
        g = gid[i];
    }
    int  g0  = __shfl_sync(0xffffffffu, g, 0);
    bool uni = __all_sync(0xffffffffu, valid && (g == g0));
    if (uni) {
#pragma unroll
        for (int o = 16; o > 0; o >>= 1)
            u += __shfl_xor_sync(0xffffffffu, u, o);
        if ((threadIdx.x & 31) == 0) {
            red_f32(&G_S[g0], u);
            red_f32(&G_CNT[g0], 32.0f);
        }
    } else if (valid) {
        red_f32(&G_S[g], u);
        red_f32(&G_CNT[g], 1.0f);
    }

    // --- last-block-done: finish with the tiny output GEMV ------------------
    __shared__ bool s_last;
    __shared__ float s_rw[8];
    __threadfence();                       // release our REDs
    __syncthreads();
    if (threadIdx.x == 0)
        s_last = (atomicAdd(&g_ticket, 1u) == nb - 1u);
    __syncthreads();
    if (!s_last) return;
    __threadfence();                       // acquire all blocks' REDs

    if (threadIdx.x < 8) {                 // rw[c] = relu(relu(W1)@W2) @ Wlast[:,c]
        int c = threadIdx.x;
        float rw = 0.0f;
#pragma unroll
        for (int k = 0; k < 8; ++k) {
            float q = 0.0f;
#pragma unroll
            for (int j = 0; j < 8; ++j)
                q += fmaxf(W1[j], 0.0f) * W2[j * 8 + k];
            rw += fmaxf(q, 0.0f) * Wlast[k * 8 + c];
        }
        s_rw[c] = rw;
    }
    __syncthreads();
    for (int t = threadIdx.x; t < G * 8; t += blockDim.x) {
        int gg = t >> 3;
        out[t] = (G_S[gg] / fmaxf(G_CNT[gg], 1.0f)) * s_rw[t & 7];
    }
    __syncthreads();
    if (threadIdx.x == 0) g_ticket = 0u;   // self-reset (sole surviving block)
}

// ---------------------------------------------------------------------------
// kernel_launch — 6 graph nodes. Scatters identical to the 260µs best.
// Inputs (metadata order): W1[8], W2[64], Wlast[64], src[E], dst[E], graph_ids[N]
// Output: G*C float32
// ---------------------------------------------------------------------------
extern "C" void kernel_launch(void* const* d_in, const int* in_sizes, int n_in,
                              void* d_out, int out_size) {
    const float* W1    = (const float*)d_in[0];
    const float* W2    = (const float*)d_in[1];
    const float* Wlast = (const float*)d_in[2];
    const int*   src   = (const int*)d_in[3];
    const int*   dst   = (const int*)d_in[4];
    const int*   gid   = (const int*)d_in[5];

    int E = in_sizes[3];
    int N = in_sizes[5];
    int G = out_size / 8;
    float* out = (float*)d_out;

    void* pbuf;
    cudaGetSymbolAddress(&pbuf, g_buf);
    cudaMemsetAsync(pbuf, 0, BUF_BYTES);   // deg + agg1 + A + S + cnt, one node

    const int TB = 256;
    int nE8 = (E + 7) / 8;
    int gE8 = (nE8 + TB - 1) / TB;
    int nN4 = (N + 3) / 4;
    int gN4 = (nN4 + TB - 1) / TB;
    unsigned gN = (unsigned)((N + TB - 1) / TB);

    k_deg        <<<gE8, TB>>>(src, dst, E);
    k_scatter1   <<<gE8, TB>>>(src, dst, E);
    k_t          <<<gN4, TB>>>(N);
    k_scatter2   <<<gE8, TB>>>(src, dst, E);
    k_pool_final <<<gN,  TB>>>(gid, W1, W2, Wlast, out, N, G, gN);
}